// round 5
// baseline (speedup 1.0000x reference)
#include <cuda_runtime.h>

#define NQ      22
#define NSTATE  (1u << NQ)
#define NLAYERS 8

typedef unsigned long long u64;

// Ping-pong statevector buffers (64 MB total; resident in L2)
__device__ float2 g_state[2][NSTATE];
// Fused single-qubit unitaries U = RX*RZ*RY (float2 form, for table build)
__device__ float2 g_U[NLAYERS][NQ][4];
// Packed duplicated coefficients (SU(2) form, 6 u64 per gate):
// [0]=dup(u00.re) [1]=dup(u00.im) [2]=dup(u01.re) [3]=dup(u01.im)
// [4]=dup(-u01.re) [5]=dup(-u00.im)
__device__ u64 g_Upk[NLAYERS][NQ][6];
// Product-state tables for layer 0: amp(g) = Phi[g>>11] * Plo[g & 0x7FF]
__device__ float2 g_Phi[2048];
__device__ float2 g_Plo[2048];

// ---------------------------------------------------------------------------
// f32x2 packed helpers (amplitude packed as (re, im) in a 64-bit reg pair)
// ---------------------------------------------------------------------------
__device__ __forceinline__ u64 pk2(float lo, float hi) {
    u64 r; asm("mov.b64 %0, {%1, %2};" : "=l"(r) : "f"(lo), "f"(hi)); return r;
}
__device__ __forceinline__ void unpk2(u64 v, float& lo, float& hi) {
    asm("mov.b64 {%0, %1}, %2;" : "=f"(lo), "=f"(hi) : "l"(v));
}
__device__ __forceinline__ u64 f2mul(u64 a, u64 b) {
    u64 r; asm("mul.rn.f32x2 %0, %1, %2;" : "=l"(r) : "l"(a), "l"(b)); return r;
}
__device__ __forceinline__ u64 f2fma(u64 a, u64 b, u64 c) {
    u64 r; asm("fma.rn.f32x2 %0, %1, %2, %3;" : "=l"(r) : "l"(a), "l"(b), "l"(c)); return r;
}
// (re, im) -> (-im, re)
__device__ __forceinline__ u64 sneg(u64 x) {
    float re, im; unpk2(x, re, im);
    unsigned nim = __float_as_uint(im) ^ 0x80000000u;
    u64 r; asm("mov.b64 %0, {%1, %2};" : "=l"(r) : "r"(nim), "r"(__float_as_uint(re)));
    return r;
}

// SU(2) gate: u11 = conj(u00), u10 = -conj(u01) -> only 6 dup coefficients
struct GateP { u64 c00r, c00i, c01r, c01i, n01r, n00i; };

__device__ __forceinline__ GateP ldgate(const u64* __restrict__ p) {
    GateP G;
    G.c00r = __ldg(p + 0); G.c00i = __ldg(p + 1);
    G.c01r = __ldg(p + 2); G.c01i = __ldg(p + 3);
    G.n01r = __ldg(p + 4); G.n00i = __ldg(p + 5);
    return G;
}

// y0 = u00*x0 + u01*x1 ; y1 = -conj(u01)*x0 + conj(u00)*x1
// 2 MUL + 6 FMA f32x2, 2 sneg on ALU pipe
__device__ __forceinline__ void bfly(const GateP& G, u64& x0, u64& x1) {
    u64 s0 = sneg(x0), s1 = sneg(x1);
    u64 y0 = f2mul(G.c00r, x0);
    y0 = f2fma(G.c00i, s0, y0);
    y0 = f2fma(G.c01r, x1, y0);
    y0 = f2fma(G.c01i, s1, y0);
    u64 y1 = f2mul(G.n01r, x0);
    y1 = f2fma(G.c01i, s0, y1);
    y1 = f2fma(G.c00r, x1, y1);
    y1 = f2fma(G.n00i, s1, y1);
    x0 = y0; x1 = y1;
}

// Apply one gate across register bit K of the 8-amp register file
template<int K>
__device__ __forceinline__ void gate_on_regbit(const u64* __restrict__ Uq, u64 a[8]) {
    GateP G = ldgate(Uq);
#pragma unroll
    for (int m = 0; m < 4; m++) {
        int j0 = ((m >> K) << (K + 1)) | (m & ((1 << K) - 1));
        bfly(G, a[j0], a[j0 | (1 << K)]);
    }
}

// Smem swizzle: all phase patterns below hit each 64-bit bank-pair <=2x/warp
__device__ __forceinline__ int SW(int i) { return i ^ ((i >> 4) & 15); }

// ---------------------------------------------------------------------------
// Prep: fused U matrices (float2 + packed), then layer-0 product tables.
// ---------------------------------------------------------------------------
__global__ void prep_kernel(const float* __restrict__ p) {
    int tid = threadIdx.x;
    if (tid < NLAYERS * NQ) {
        int l = tid / NQ, q = tid % NQ;
        float ty = p[l * 3 * NQ + q];
        float tz = p[l * 3 * NQ + NQ + q];
        float tx = p[l * 3 * NQ + 2 * NQ + q];
        float cy = cosf(0.5f * ty), sy = sinf(0.5f * ty);
        float cz = cosf(0.5f * tz), sz = sinf(0.5f * tz);
        float cx = cosf(0.5f * tx), sx = sinf(0.5f * tx);
        float2 em = make_float2(cz, -sz);
        float2 ep = make_float2(cz, sz);
        float2 u00 = make_float2(cx * cy * em.x + sx * sy * ep.y,
                                 cx * cy * em.y - sx * sy * ep.x);
        float2 u01 = make_float2(-cx * sy * em.x + sx * cy * ep.y,
                                 -cx * sy * em.y - sx * cy * ep.x);
        float2 u10 = make_float2(sx * cy * em.y + cx * sy * ep.x,
                                 -sx * cy * em.x + cx * sy * ep.y);
        float2 u11 = make_float2(-sx * sy * em.y + cx * cy * ep.x,
                                 sx * sy * em.x + cx * cy * ep.y);
        g_U[l][q][0] = u00; g_U[l][q][1] = u01;
        g_U[l][q][2] = u10; g_U[l][q][3] = u11;
        u64* pkd = g_Upk[l][q];
        pkd[0] = pk2(u00.x, u00.x); pkd[1] = pk2(u00.y, u00.y);
        pkd[2] = pk2(u01.x, u01.x); pkd[3] = pk2(u01.y, u01.y);
        pkd[4] = pk2(-u01.x, -u01.x); pkd[5] = pk2(-u00.y, -u00.y);
    }
    __syncthreads();
    for (int i = tid; i < 2048; i += blockDim.x) {
        float2 ph = make_float2(1.f, 0.f);
        float2 pl = make_float2(1.f, 0.f);
        for (int q = 0; q <= 10; q++) {
            int b = (i >> (10 - q)) & 1;
            float2 u = g_U[0][q][b * 2];
            ph = make_float2(ph.x * u.x - ph.y * u.y, ph.x * u.y + ph.y * u.x);
        }
        for (int q = 11; q <= 21; q++) {
            int b = (i >> (21 - q)) & 1;
            float2 u = g_U[0][q][b * 2];
            pl = make_float2(pl.x * u.x - pl.y * u.y, pl.x * u.y + pl.y * u.x);
        }
        g_Phi[i] = ph;
        g_Plo[i] = pl;
    }
}

// ---------------------------------------------------------------------------
// L kernel: tile = 4096 contiguous amps (bits 0..11), 12 gates on bits 0..11
// (qubits 10..21). blockIdx = global bits 12..21. Load folds previous layer's
// CNOT chain via gray addressing; first=1 synthesizes the layer-0 product
// state. 4 phases of 3 gates, 3 smem transposes. 8 amps/thread.
// ---------------------------------------------------------------------------
__global__ void __launch_bounds__(512, 3) kernelL(int layer, int srcIdx, int dstIdx, int first) {
    extern __shared__ u64 sh[];
    const int t = threadIdx.x;                 // 9 bits
    const unsigned h = blockIdx.x;             // global bits 12..21 (10 bits)
    const unsigned ghi = h ^ (h >> 1);
    const unsigned c11 = (h & 1u) << 11;
    const u64* __restrict__ Ul = &g_Upk[layer][0][0];
    u64 a[8];

    // ---- Phase A: i = (r<<9)|t ; reg bits local 9..11 -> qubits 12,11,10
    if (first) {
#pragma unroll
        for (int r = 0; r < 8; r++) {
            unsigned i = (r << 9) | t;
            unsigned glo = (i ^ (i >> 1)) ^ c11;
            float2 ph = g_Phi[(ghi << 1) | (glo >> 11)];
            float2 pl = g_Plo[glo & 2047];
            a[r] = pk2(ph.x * pl.x - ph.y * pl.y, ph.x * pl.y + ph.y * pl.x);
        }
    } else {
        const float2* __restrict__ src = g_state[srcIdx] + ((size_t)ghi << 12);
#pragma unroll
        for (int r = 0; r < 8; r++) {
            unsigned i = (r << 9) | t;
            unsigned glo = (i ^ (i >> 1)) ^ c11;
            float2 v = __ldg(&src[glo]);
            a[r] = pk2(v.x, v.y);
        }
    }
    gate_on_regbit<0>(Ul + 12 * 6, a);
    gate_on_regbit<1>(Ul + 11 * 6, a);
    gate_on_regbit<2>(Ul + 10 * 6, a);
#pragma unroll
    for (int r = 0; r < 8; r++) sh[SW((r << 9) | t)] = a[r];
    __syncthreads();

    // ---- Phase B: i = (t<<3)|r ; reg bits local 0..2 -> qubits 21,20,19
#pragma unroll
    for (int r = 0; r < 8; r++) a[r] = sh[SW((t << 3) | r)];
    gate_on_regbit<0>(Ul + 21 * 6, a);
    gate_on_regbit<1>(Ul + 20 * 6, a);
    gate_on_regbit<2>(Ul + 19 * 6, a);
#pragma unroll
    for (int r = 0; r < 8; r++) sh[SW((t << 3) | r)] = a[r];
    __syncthreads();

    // ---- Phase C: i = ((t>>3)<<6)|(r<<3)|(t&7) ; local 3..5 -> qubits 18,17,16
    const int c_hi = t >> 3, c_lo = t & 7;
#pragma unroll
    for (int r = 0; r < 8; r++) a[r] = sh[SW((c_hi << 6) | (r << 3) | c_lo)];
    gate_on_regbit<0>(Ul + 18 * 6, a);
    gate_on_regbit<1>(Ul + 17 * 6, a);
    gate_on_regbit<2>(Ul + 16 * 6, a);
#pragma unroll
    for (int r = 0; r < 8; r++) sh[SW((c_hi << 6) | (r << 3) | c_lo)] = a[r];
    __syncthreads();

    // ---- Phase D: i = ((t>>6)<<9)|(r<<6)|(t&63) ; local 6..8 -> qubits 15,14,13
    const int d_hi = t >> 6, d_lo = t & 63;
#pragma unroll
    for (int r = 0; r < 8; r++) a[r] = sh[SW((d_hi << 9) | (r << 6) | d_lo)];
    gate_on_regbit<0>(Ul + 15 * 6, a);
    gate_on_regbit<1>(Ul + 14 * 6, a);
    gate_on_regbit<2>(Ul + 13 * 6, a);

    float2* __restrict__ dst = g_state[dstIdx] + ((size_t)h << 12);
#pragma unroll
    for (int r = 0; r < 8; r++) {
        float re, im; unpk2(a[r], re, im);
        dst[(d_hi << 9) | (r << 6) | d_lo] = make_float2(re, im);
    }
}

// ---------------------------------------------------------------------------
// H kernel: tile bits {0..1} U {12..21} (4096 amps), 10 gates on global bits
// 12..21 (qubits 0..9). blockIdx = global bits 2..11 (10 bits). Optionally
// folds final CNOT chain + |amp|^2 into the store (probs != nullptr).
// Local map: local 0..1 = global 0..1, local 2..11 = global 12..21.
// j(i) = ((i>>2)<<12) | (f<<2) | (i&3). 4 phases (3+3+3+1), 3 transposes.
// ---------------------------------------------------------------------------
__global__ void __launch_bounds__(512, 3) kernelH(int layer, int srcIdx, int dstIdx,
                                                  float* __restrict__ probs) {
    extern __shared__ u64 sh[];
    const int t = threadIdx.x;                 // 9 bits
    const unsigned f = blockIdx.x;             // global bits 2..11 (10 bits)
    const u64* __restrict__ Ul = &g_Upk[layer][0][0];
    u64 a[8];

    // ---- Phase A: i = (r<<9)|t ; reg bits local 9..11 = global 19..21 -> qubits 2,1,0
    {
        const float2* __restrict__ src = g_state[srcIdx];
        const unsigned jt = ((unsigned)(t >> 2) << 12) | (f << 2) | (unsigned)(t & 3);
#pragma unroll
        for (int r = 0; r < 8; r++) {
            float2 v = __ldg(&src[jt | (r << 19)]);
            a[r] = pk2(v.x, v.y);
        }
    }
    gate_on_regbit<0>(Ul + 2 * 6, a);
    gate_on_regbit<1>(Ul + 1 * 6, a);
    gate_on_regbit<2>(Ul + 0 * 6, a);
#pragma unroll
    for (int r = 0; r < 8; r++) sh[SW((r << 9) | t)] = a[r];
    __syncthreads();

    // ---- Phase B: i = ((t>>2)<<5)|(r<<2)|(t&3) ; local 2..4 = global 12..14 -> q 9,8,7
    const int b_hi = t >> 2, b_lo = t & 3;
#pragma unroll
    for (int r = 0; r < 8; r++) a[r] = sh[SW((b_hi << 5) | (r << 2) | b_lo)];
    gate_on_regbit<0>(Ul + 9 * 6, a);
    gate_on_regbit<1>(Ul + 8 * 6, a);
    gate_on_regbit<2>(Ul + 7 * 6, a);
#pragma unroll
    for (int r = 0; r < 8; r++) sh[SW((b_hi << 5) | (r << 2) | b_lo)] = a[r];
    __syncthreads();

    // ---- Phase C: i = ((t>>5)<<8)|(r<<5)|(t&31) ; local 5..7 = global 15..17 -> q 6,5,4
    const int ch = t >> 5, cl = t & 31;
#pragma unroll
    for (int r = 0; r < 8; r++) a[r] = sh[SW((ch << 8) | (r << 5) | cl)];
    gate_on_regbit<0>(Ul + 6 * 6, a);
    gate_on_regbit<1>(Ul + 5 * 6, a);
    gate_on_regbit<2>(Ul + 4 * 6, a);
#pragma unroll
    for (int r = 0; r < 8; r++) sh[SW((ch << 8) | (r << 5) | cl)] = a[r];
    __syncthreads();

    // ---- Phase D: i = ((t>>8)<<11)|(r<<8)|(t&255) ; reg bit 0 = local 8 = global 18 -> q 3
    const int dh = t >> 8, dl = t & 255;
#pragma unroll
    for (int r = 0; r < 8; r++) a[r] = sh[SW((dh << 11) | (r << 8) | dl)];
    gate_on_regbit<0>(Ul + 3 * 6, a);

    if (probs) {
#pragma unroll
        for (int r = 0; r < 8; r++) {
            int i = (dh << 11) | (r << 8) | dl;
            unsigned j = (((unsigned)i >> 2) << 12) | (f << 2) | (unsigned)(i & 3);
            unsigned o = j;
            o ^= o >> 1; o ^= o >> 2; o ^= o >> 4; o ^= o >> 8; o ^= o >> 16;
            float re, im; unpk2(a[r], re, im);
            probs[o] = fmaf(re, re, im * im);
        }
    } else {
        float2* __restrict__ dst = g_state[dstIdx];
#pragma unroll
        for (int r = 0; r < 8; r++) {
            int i = (dh << 11) | (r << 8) | dl;
            unsigned j = (((unsigned)i >> 2) << 12) | (f << 2) | (unsigned)(i & 3);
            float re, im; unpk2(a[r], re, im);
            dst[j] = make_float2(re, im);
        }
    }
}

// ---------------------------------------------------------------------------
extern "C" void kernel_launch(void* const* d_in, const int* in_sizes, int n_in,
                              void* d_out, int out_size) {
    (void)in_sizes; (void)n_in; (void)out_size;
    const float* params = (const float*)d_in[0];
    float* out = (float*)d_out;

    prep_kernel<<<1, 1024>>>(params);

    // Layer 0 folded into tables; layer-(l-1) CNOT chain folded into L's gray
    // load; layer-7 chain folded into the prob scatter.
    kernelL<<<1024, 512, 32768>>>(1, /*src*/1, /*dst*/0, /*first*/1);
    kernelH<<<1024, 512, 32768>>>(1, 0, 1, nullptr);
    for (int ll = 2; ll <= 7; ll++) {
        kernelL<<<1024, 512, 32768>>>(ll, 1, 0, 0);
        kernelH<<<1024, 512, 32768>>>(ll, 0, 1, (ll == 7) ? out : nullptr);
    }
}

// round 6
// speedup vs baseline: 1.2337x; 1.2337x over previous
#include <cuda_runtime.h>

#define NQ      22
#define NSTATE  (1u << NQ)
#define NLAYERS 8

typedef unsigned long long u64;

// Ping-pong statevector buffers (64 MB total; resident in L2)
__device__ float2 g_state[2][NSTATE];
// Fused single-qubit unitaries U = RX*RZ*RY (float2 form, for table build)
__device__ float2 g_U[NLAYERS][NQ][4];
// Packed duplicated coefficients (SU(2) form, 6 u64 per gate):
// [0]=dup(u00.re) [1]=dup(u00.im) [2]=dup(u01.re) [3]=dup(u01.im)
// [4]=dup(-u01.re) [5]=dup(-u00.im)
__device__ u64 g_Upk[NLAYERS][NQ][6];
// Product-state tables for layer 0: amp(g) = Phi[g>>11] * Plo[g & 0x7FF]
__device__ float2 g_Phi[2048];
__device__ float2 g_Plo[2048];

// ---------------------------------------------------------------------------
// f32x2 packed helpers (amplitude packed as (re, im) in a 64-bit reg pair)
// ---------------------------------------------------------------------------
__device__ __forceinline__ u64 pk2(float lo, float hi) {
    u64 r; asm("mov.b64 %0, {%1, %2};" : "=l"(r) : "f"(lo), "f"(hi)); return r;
}
__device__ __forceinline__ void unpk2(u64 v, float& lo, float& hi) {
    asm("mov.b64 {%0, %1}, %2;" : "=f"(lo), "=f"(hi) : "l"(v));
}
__device__ __forceinline__ u64 f2mul(u64 a, u64 b) {
    u64 r; asm("mul.rn.f32x2 %0, %1, %2;" : "=l"(r) : "l"(a), "l"(b)); return r;
}
__device__ __forceinline__ u64 f2fma(u64 a, u64 b, u64 c) {
    u64 r; asm("fma.rn.f32x2 %0, %1, %2, %3;" : "=l"(r) : "l"(a), "l"(b), "l"(c)); return r;
}
// (re, im) -> (-im, re)
__device__ __forceinline__ u64 sneg(u64 x) {
    float re, im; unpk2(x, re, im);
    unsigned nim = __float_as_uint(im) ^ 0x80000000u;
    u64 r; asm("mov.b64 %0, {%1, %2};" : "=l"(r) : "r"(nim), "r"(__float_as_uint(re)));
    return r;
}

// SU(2) gate: u11 = conj(u00), u10 = -conj(u01) -> only 6 dup coefficients
struct GateP { u64 c00r, c00i, c01r, c01i, n01r, n00i; };

// Coefficients live in shared memory (broadcast LDS, conflict-free)
__device__ __forceinline__ GateP ldgate(const u64* p) {
    GateP G;
    G.c00r = p[0]; G.c00i = p[1];
    G.c01r = p[2]; G.c01i = p[3];
    G.n01r = p[4]; G.n00i = p[5];
    return G;
}

// y0 = u00*x0 + u01*x1 ; y1 = -conj(u01)*x0 + conj(u00)*x1
// 2 MUL + 6 FMA f32x2, 2 sneg on ALU pipe
__device__ __forceinline__ void bfly(const GateP& G, u64& x0, u64& x1) {
    u64 s0 = sneg(x0), s1 = sneg(x1);
    u64 y0 = f2mul(G.c00r, x0);
    y0 = f2fma(G.c00i, s0, y0);
    y0 = f2fma(G.c01r, x1, y0);
    y0 = f2fma(G.c01i, s1, y0);
    u64 y1 = f2mul(G.n01r, x0);
    y1 = f2fma(G.c01i, s0, y1);
    y1 = f2fma(G.c00r, x1, y1);
    y1 = f2fma(G.n00i, s1, y1);
    x0 = y0; x1 = y1;
}

// Apply one gate across register bit K of the 16-amp register file
template<int K>
__device__ __forceinline__ void gate_on_regbit(const u64* Uq, u64 a[16]) {
    GateP G = ldgate(Uq);
#pragma unroll
    for (int m = 0; m < 8; m++) {
        int j0 = ((m >> K) << (K + 1)) | (m & ((1 << K) - 1));
        bfly(G, a[j0], a[j0 | (1 << K)]);
    }
}

// Swizzles (verified conflict-free / half-warp-only for each kernel's patterns)
__device__ __forceinline__ int SWL(int i) { return i ^ ((i >> 4) & 15); }   // kernelL
__device__ __forceinline__ int SWH(int i) { return i ^ ((i >> 2) & 24); }   // kernelH

// ---------------------------------------------------------------------------
// Prep: fused U matrices (float2 + packed), then layer-0 product tables.
// ---------------------------------------------------------------------------
__global__ void prep_kernel(const float* __restrict__ p) {
    int tid = threadIdx.x;
    if (tid < NLAYERS * NQ) {
        int l = tid / NQ, q = tid % NQ;
        float ty = p[l * 3 * NQ + q];
        float tz = p[l * 3 * NQ + NQ + q];
        float tx = p[l * 3 * NQ + 2 * NQ + q];
        float cy = cosf(0.5f * ty), sy = sinf(0.5f * ty);
        float cz = cosf(0.5f * tz), sz = sinf(0.5f * tz);
        float cx = cosf(0.5f * tx), sx = sinf(0.5f * tx);
        float2 em = make_float2(cz, -sz);
        float2 ep = make_float2(cz, sz);
        float2 u00 = make_float2(cx * cy * em.x + sx * sy * ep.y,
                                 cx * cy * em.y - sx * sy * ep.x);
        float2 u01 = make_float2(-cx * sy * em.x + sx * cy * ep.y,
                                 -cx * sy * em.y - sx * cy * ep.x);
        float2 u10 = make_float2(sx * cy * em.y + cx * sy * ep.x,
                                 -sx * cy * em.x + cx * sy * ep.y);
        float2 u11 = make_float2(-sx * sy * em.y + cx * cy * ep.x,
                                 sx * sy * em.x + cx * cy * ep.y);
        g_U[l][q][0] = u00; g_U[l][q][1] = u01;
        g_U[l][q][2] = u10; g_U[l][q][3] = u11;
        u64* pkd = g_Upk[l][q];
        pkd[0] = pk2(u00.x, u00.x); pkd[1] = pk2(u00.y, u00.y);
        pkd[2] = pk2(u01.x, u01.x); pkd[3] = pk2(u01.y, u01.y);
        pkd[4] = pk2(-u01.x, -u01.x); pkd[5] = pk2(-u00.y, -u00.y);
    }
    __syncthreads();
    for (int i = tid; i < 2048; i += blockDim.x) {
        float2 ph = make_float2(1.f, 0.f);
        float2 pl = make_float2(1.f, 0.f);
        for (int q = 0; q <= 10; q++) {
            int b = (i >> (10 - q)) & 1;
            float2 u = g_U[0][q][b * 2];
            ph = make_float2(ph.x * u.x - ph.y * u.y, ph.x * u.y + ph.y * u.x);
        }
        for (int q = 11; q <= 21; q++) {
            int b = (i >> (21 - q)) & 1;
            float2 u = g_U[0][q][b * 2];
            pl = make_float2(pl.x * u.x - pl.y * u.y, pl.x * u.y + pl.y * u.x);
        }
        g_Phi[i] = ph;
        g_Plo[i] = pl;
    }
}

// Shared memory layout: sh[0..8191] = amplitude tile, sh[8192..] = gate coefs
#define SMEM_WORDS (8192 + 72)
#define SMEM_BYTES (SMEM_WORDS * 8)

// ---------------------------------------------------------------------------
// L kernel: tile = 8192 contiguous amps (bits 0..12), 12 gates on bits 0..11
// (qubits 10..21). Load folds previous layer's CNOT chain via gray addressing;
// first=1 synthesizes the layer-0 product state. 3 phases, 2 smem transposes.
// Gate coefficients staged once into smem (broadcast reads thereafter).
// ---------------------------------------------------------------------------
__global__ void __launch_bounds__(512, 2) kernelL(int layer, int srcIdx, int dstIdx, int first) {
    extern __shared__ u64 sh[];
    u64* shC = sh + 8192;
    const int t = threadIdx.x;                 // 9 bits
    const unsigned h = blockIdx.x;             // global bits 13..21 (9 bits)
    const unsigned ghi = h ^ (h >> 1);
    const unsigned c12 = (h & 1u) << 12;
    u64 a[16];

    // Stage the 12 gates' coefficients (qubits 10..21, contiguous 72 u64)
    if (t < 72) shC[t] = __ldg(&g_Upk[layer][10][0] + t);

    const int b12 = t >> 8, t8 = t & 255;
    // ---- Phase A: i = (b12<<12)|(r<<8)|t8 ; reg bits local 8..11 -> qubit 13-k
    if (first) {
#pragma unroll
        for (int r = 0; r < 16; r++) {
            unsigned i = (b12 << 12) | (r << 8) | t8;
            unsigned glo = (i ^ (i >> 1)) ^ c12;
            float2 ph = g_Phi[(ghi << 2) | (glo >> 11)];
            float2 pl = g_Plo[glo & 2047];
            a[r] = pk2(ph.x * pl.x - ph.y * pl.y, ph.x * pl.y + ph.y * pl.x);
        }
    } else {
        const float2* __restrict__ src = g_state[srcIdx] + ((size_t)ghi << 13);
#pragma unroll
        for (int r = 0; r < 16; r++) {
            unsigned i = (b12 << 12) | (r << 8) | t8;
            unsigned glo = (i ^ (i >> 1)) ^ c12;
            float2 v = __ldg(&src[glo]);
            a[r] = pk2(v.x, v.y);
        }
    }
    __syncthreads();                            // coefs visible
    gate_on_regbit<0>(shC + (13 - 10) * 6, a);
    gate_on_regbit<1>(shC + (12 - 10) * 6, a);
    gate_on_regbit<2>(shC + (11 - 10) * 6, a);
    gate_on_regbit<3>(shC + (10 - 10) * 6, a);
#pragma unroll
    for (int r = 0; r < 16; r++) sh[SWL((b12 << 12) | (r << 8) | t8)] = a[r];
    __syncthreads();

    // ---- Phase B: i = (t<<4)|r ; reg bits local 0..3 -> qubit 21-k
#pragma unroll
    for (int r = 0; r < 16; r++) a[r] = sh[SWL((t << 4) | r)];
    gate_on_regbit<0>(shC + (21 - 10) * 6, a);
    gate_on_regbit<1>(shC + (20 - 10) * 6, a);
    gate_on_regbit<2>(shC + (19 - 10) * 6, a);
    gate_on_regbit<3>(shC + (18 - 10) * 6, a);
#pragma unroll
    for (int r = 0; r < 16; r++) sh[SWL((t << 4) | r)] = a[r];
    __syncthreads();

    // ---- Phase C: i = (hi5<<8)|(r<<4)|lo4 ; reg bits local 4..7 -> qubit 17-k
    const int hi5 = t >> 4, lo4 = t & 15;
#pragma unroll
    for (int r = 0; r < 16; r++) a[r] = sh[SWL((hi5 << 8) | (r << 4) | lo4)];
    gate_on_regbit<0>(shC + (17 - 10) * 6, a);
    gate_on_regbit<1>(shC + (16 - 10) * 6, a);
    gate_on_regbit<2>(shC + (15 - 10) * 6, a);
    gate_on_regbit<3>(shC + (14 - 10) * 6, a);

    float2* __restrict__ dst = g_state[dstIdx] + ((size_t)h << 13);
#pragma unroll
    for (int r = 0; r < 16; r++) {
        float re, im; unpk2(a[r], re, im);
        dst[(hi5 << 8) | (r << 4) | lo4] = make_float2(re, im);
    }
}

// ---------------------------------------------------------------------------
// H kernel: tile bits {0..2} U {12..21} (8192 amps), 10 gates on global bits
// 12..21 (qubits 0..9). blockIdx = global bits 3..11. Optionally folds final
// CNOT chain + |amp|^2 into the store (probs != nullptr). 3 phases.
// Local map: local 0..2 = global 0..2, local 3..12 = global 12..21.
// j(i) = ((i>>3)<<12) | (f<<3) | (i&7)
// ---------------------------------------------------------------------------
__global__ void __launch_bounds__(512, 2) kernelH(int layer, int srcIdx, int dstIdx,
                                                  float* __restrict__ probs) {
    extern __shared__ u64 sh[];
    u64* shC = sh + 8192;
    const int t = threadIdx.x;                 // 9 bits
    const unsigned f = blockIdx.x;             // global bits 3..11 (9 bits)
    u64 a[16];

    // Stage the 10 gates' coefficients (qubits 0..9, contiguous 60 u64)
    if (t < 60) shC[t] = __ldg(&g_Upk[layer][0][0] + t);

    // ---- Phase A: i = (r<<9)|t ; reg bits local 9..12 = global 18..21 -> qubit 3-k
    const unsigned jt = ((unsigned)(t >> 3) << 12) | (f << 3) | (unsigned)(t & 7);
    {
        const float2* __restrict__ src = g_state[srcIdx];
#pragma unroll
        for (int r = 0; r < 16; r++) {
            float2 v = __ldg(&src[jt | (r << 18)]);
            a[r] = pk2(v.x, v.y);
        }
    }
    __syncthreads();                            // coefs visible
    gate_on_regbit<0>(shC + 3 * 6, a);
    gate_on_regbit<1>(shC + 2 * 6, a);
    gate_on_regbit<2>(shC + 1 * 6, a);
    gate_on_regbit<3>(shC + 0 * 6, a);
#pragma unroll
    for (int r = 0; r < 16; r++) sh[SWH((r << 9) | t)] = a[r];
    __syncthreads();

    // ---- Phase B: i = (hi4<<9)|(r<<5)|lo5 ; local 5..8 = global 14..17 -> qubit 7-k
    const int hi4 = t >> 5, lo5 = t & 31;
#pragma unroll
    for (int r = 0; r < 16; r++) a[r] = sh[SWH((hi4 << 9) | (r << 5) | lo5)];
    gate_on_regbit<0>(shC + 7 * 6, a);
    gate_on_regbit<1>(shC + 6 * 6, a);
    gate_on_regbit<2>(shC + 5 * 6, a);
    gate_on_regbit<3>(shC + 4 * 6, a);
#pragma unroll
    for (int r = 0; r < 16; r++) sh[SWH((hi4 << 9) | (r << 5) | lo5)] = a[r];
    __syncthreads();

    // ---- Phase C: reg bits: r0,r1 -> local 3,4 (qubits 9,8); r2,r3 -> local 9,10
    // i = (t_c<<11)|(rf<<9)|(t_b<<5)|(rg<<3)|t_a
    const int t_a = t & 7, t_b = (t >> 3) & 15, t_c = t >> 7;
#pragma unroll
    for (int r = 0; r < 16; r++) {
        int i = (t_c << 11) | ((r >> 2) << 9) | (t_b << 5) | ((r & 3) << 3) | t_a;
        a[r] = sh[SWH(i)];
    }
    gate_on_regbit<0>(shC + 9 * 6, a);     // local 3 = global 12 -> qubit 9
    gate_on_regbit<1>(shC + 8 * 6, a);     // local 4 = global 13 -> qubit 8

    if (probs) {
#pragma unroll
        for (int r = 0; r < 16; r++) {
            int i = (t_c << 11) | ((r >> 2) << 9) | (t_b << 5) | ((r & 3) << 3) | t_a;
            unsigned j = (((unsigned)i >> 3) << 12) | (f << 3) | (unsigned)(i & 7);
            unsigned o = j;
            o ^= o >> 1; o ^= o >> 2; o ^= o >> 4; o ^= o >> 8; o ^= o >> 16;
            float re, im; unpk2(a[r], re, im);
            probs[o] = fmaf(re, re, im * im);
        }
    } else {
        float2* __restrict__ dst = g_state[dstIdx];
#pragma unroll
        for (int r = 0; r < 16; r++) {
            int i = (t_c << 11) | ((r >> 2) << 9) | (t_b << 5) | ((r & 3) << 3) | t_a;
            unsigned j = (((unsigned)i >> 3) << 12) | (f << 3) | (unsigned)(i & 7);
            float re, im; unpk2(a[r], re, im);
            dst[j] = make_float2(re, im);
        }
    }
}

// ---------------------------------------------------------------------------
extern "C" void kernel_launch(void* const* d_in, const int* in_sizes, int n_in,
                              void* d_out, int out_size) {
    (void)in_sizes; (void)n_in; (void)out_size;
    const float* params = (const float*)d_in[0];
    float* out = (float*)d_out;

    cudaFuncSetAttribute(kernelL, cudaFuncAttributeMaxDynamicSharedMemorySize, SMEM_BYTES);
    cudaFuncSetAttribute(kernelH, cudaFuncAttributeMaxDynamicSharedMemorySize, SMEM_BYTES);

    prep_kernel<<<1, 1024>>>(params);

    // Layer 0 folded into tables; layer-(l-1) CNOT chain folded into L's gray
    // load; layer-7 chain folded into the prob scatter.
    kernelL<<<512, 512, SMEM_BYTES>>>(1, /*src*/1, /*dst*/0, /*first*/1);
    kernelH<<<512, 512, SMEM_BYTES>>>(1, 0, 1, nullptr);
    for (int ll = 2; ll <= 7; ll++) {
        kernelL<<<512, 512, SMEM_BYTES>>>(ll, 1, 0, 0);
        kernelH<<<512, 512, SMEM_BYTES>>>(ll, 0, 1, (ll == 7) ? out : nullptr);
    }
}

// round 8
// speedup vs baseline: 1.3349x; 1.0820x over previous
#include <cuda_runtime.h>

#define NQ      22
#define NSTATE  (1u << NQ)
#define NLAYERS 8

typedef unsigned long long u64;

// Ping-pong statevector buffers (64 MB total; resident in L2)
__device__ float2 g_state[2][NSTATE];
// Fused single-qubit unitaries U = RX*RZ*RY (float2, for layer-0 tables)
__device__ float2 g_U[NLAYERS][NQ][4];
// ZYZ real-rotation coefficients per gate: [0]=dup(c) [1]=dup(s) [2]=dup(-s)
__device__ u64 g_Rpk[NLAYERS][NQ][3];
// ZYZ half-angles: U = diag(e^{-ipA},e^{ipA}) * R(c,s) * diag(e^{-ipB},e^{ipB})
__device__ float g_pA[NLAYERS][NQ];
__device__ float g_pB[NLAYERS][NQ];
// Diagonal-phase tables (per layer, index split 11 hi / 11 lo of global index)
__device__ float2 g_BTlo[NLAYERS][2048];   // pre-diag  (applied at L load)
__device__ float2 g_BThi[NLAYERS][2048];
__device__ float2 g_ATlo[NLAYERS][2048];   // post-diag (applied at H store)
__device__ float2 g_AThi[NLAYERS][2048];
// Product-state tables for layer 0: amp(g) = Phi[g>>11] * Plo[g & 0x7FF]
__device__ float2 g_Phi[2048];
__device__ float2 g_Plo[2048];

// ---------------------------------------------------------------------------
// f32x2 packed helpers (amplitude packed as (re, im) in a 64-bit reg pair)
// ---------------------------------------------------------------------------
__device__ __forceinline__ u64 pk2(float lo, float hi) {
    u64 r; asm("mov.b64 %0, {%1, %2};" : "=l"(r) : "f"(lo), "f"(hi)); return r;
}
__device__ __forceinline__ void unpk2(u64 v, float& lo, float& hi) {
    asm("mov.b64 {%0, %1}, %2;" : "=f"(lo), "=f"(hi) : "l"(v));
}
__device__ __forceinline__ u64 f2mul(u64 a, u64 b) {
    u64 r; asm("mul.rn.f32x2 %0, %1, %2;" : "=l"(r) : "l"(a), "l"(b)); return r;
}
__device__ __forceinline__ u64 f2fma(u64 a, u64 b, u64 c) {
    u64 r; asm("fma.rn.f32x2 %0, %1, %2, %3;" : "=l"(r) : "l"(a), "l"(b), "l"(c)); return r;
}

__device__ __forceinline__ float2 cmulf(float2 a, float2 b) {
    return make_float2(a.x * b.x - a.y * b.y, a.x * b.y + a.y * b.x);
}
// multiply packed amp by scalar complex phase w
__device__ __forceinline__ u64 apply_phase(float2 w, u64 x) {
    float re, im; unpk2(x, re, im);
    return pk2(w.x * re - w.y * im, w.x * im + w.y * re);
}

// Real Givens butterfly: y0 = c*x0 - s*x1 ; y1 = s*x0 + c*x1  (4 f32x2 ops)
__device__ __forceinline__ void rbfly(u64 c, u64 s, u64 ns, u64& x0, u64& x1) {
    u64 y0 = f2fma(c, x0, f2mul(ns, x1));
    u64 y1 = f2fma(c, x1, f2mul(s, x0));
    x0 = y0; x1 = y1;
}

// Apply one real rotation across register bit K of the 16-amp register file
template<int K>
__device__ __forceinline__ void gate_on_regbit(const u64* Uq, u64 a[16]) {
    u64 c = Uq[0], s = Uq[1], ns = Uq[2];
#pragma unroll
    for (int m = 0; m < 8; m++) {
        int j0 = ((m >> K) << (K + 1)) | (m & ((1 << K) - 1));
        rbfly(c, s, ns, a[j0], a[j0 | (1 << K)]);
    }
}

// Swizzles (verified conflict-free / half-warp-only for each kernel's patterns)
__device__ __forceinline__ int SWL(int i) { return i ^ ((i >> 4) & 15); }   // kernelL
__device__ __forceinline__ int SWH(int i) { return i ^ ((i >> 2) & 24); }   // kernelH

// ---------------------------------------------------------------------------
// Prep: fused U, ZYZ decomposition, diag tables, layer-0 product tables.
// ---------------------------------------------------------------------------
__global__ void prep_kernel(const float* __restrict__ p) {
    int tid = threadIdx.x;
    if (tid < NLAYERS * NQ) {
        int l = tid / NQ, q = tid % NQ;
        float ty = p[l * 3 * NQ + q];
        float tz = p[l * 3 * NQ + NQ + q];
        float tx = p[l * 3 * NQ + 2 * NQ + q];
        float cy = cosf(0.5f * ty), sy = sinf(0.5f * ty);
        float cz = cosf(0.5f * tz), sz = sinf(0.5f * tz);
        float cx = cosf(0.5f * tx), sx = sinf(0.5f * tx);
        float2 em = make_float2(cz, -sz);
        float2 ep = make_float2(cz, sz);
        float2 u00 = make_float2(cx * cy * em.x + sx * sy * ep.y,
                                 cx * cy * em.y - sx * sy * ep.x);
        float2 u01 = make_float2(-cx * sy * em.x + sx * cy * ep.y,
                                 -cx * sy * em.y - sx * cy * ep.x);
        float2 u10 = make_float2(sx * cy * em.y + cx * sy * ep.x,
                                 -sx * cy * em.x + cx * sy * ep.y);
        float2 u11 = make_float2(-sx * sy * em.y + cx * cy * ep.x,
                                 sx * sy * em.x + cx * cy * ep.y);
        g_U[l][q][0] = u00; g_U[l][q][1] = u01;
        g_U[l][q][2] = u10; g_U[l][q][3] = u11;
        // ZYZ: U = diag(e^{-ipA},e^{ipA}) * [[c,-s],[s,c]] * diag(e^{-ipB},e^{ipB})
        float c = sqrtf(u00.x * u00.x + u00.y * u00.y);
        float s = sqrtf(u01.x * u01.x + u01.y * u01.y);
        float p00 = atan2f(u00.y, u00.x);
        float p01 = atan2f(u01.y, u01.x);
        const float PI = 3.14159265358979f;
        float pA = 0.5f * (-p00 - p01 + PI);
        float pB = 0.5f * (-p00 + p01 - PI);
        g_pA[l][q] = pA; g_pB[l][q] = pB;
        g_Rpk[l][q][0] = pk2(c, c);
        g_Rpk[l][q][1] = pk2(s, s);
        g_Rpk[l][q][2] = pk2(-s, -s);
    }
    __syncthreads();
    // Layer-0 product tables (full complex U_0, no decomposition)
    for (int i = tid; i < 2048; i += blockDim.x) {
        float2 ph = make_float2(1.f, 0.f);
        float2 pl = make_float2(1.f, 0.f);
        for (int q = 0; q <= 10; q++) {
            int b = (i >> (10 - q)) & 1;
            ph = cmulf(ph, g_U[0][q][b * 2]);
        }
        for (int q = 11; q <= 21; q++) {
            int b = (i >> (21 - q)) & 1;
            pl = cmulf(pl, g_U[0][q][b * 2]);
        }
        g_Phi[i] = ph;
        g_Plo[i] = pl;
    }
    // Diagonal-phase tables for layers 1..7.
    // lo: global bits 0..10  (bit b <-> qubit 21-b);  hi: bits 11..21 (bit k <-> qubit 10-k)
    for (int idx = tid; idx < NLAYERS * 2048; idx += blockDim.x) {
        int l = idx >> 11, x = idx & 2047;
        if (l >= 1) {
            float aBlo = 0.f, aBhi = 0.f, aAlo = 0.f, aAhi = 0.f;
            for (int b = 0; b < 11; b++) {
                float sgn = ((x >> b) & 1) ? 1.f : -1.f;
                aBlo += sgn * g_pB[l][21 - b];
                aBhi += sgn * g_pB[l][10 - b];
                aAlo += sgn * g_pA[l][21 - b];
                aAhi += sgn * g_pA[l][10 - b];
            }
            g_BTlo[l][x] = make_float2(cosf(aBlo), sinf(aBlo));
            g_BThi[l][x] = make_float2(cosf(aBhi), sinf(aBhi));
            g_ATlo[l][x] = make_float2(cosf(aAlo), sinf(aAlo));
            g_AThi[l][x] = make_float2(cosf(aAhi), sinf(aAhi));
        }
    }
}

// Shared memory layout: sh[0..8191] = amplitude tile, sh[8192..] = gate coefs
#define SMEM_WORDS (8192 + 40)
#define SMEM_BYTES (SMEM_WORDS * 8)

// ---------------------------------------------------------------------------
// L kernel: tile = 8192 contiguous amps (bits 0..12), 12 real rotations on
// bits 0..11 (qubits 10..21). Load folds previous layer's CNOT chain via gray
// addressing AND applies B_l pre-diag phase; first=1 synthesizes the layer-0
// product state. 3 phases, 2 smem transposes.
// ---------------------------------------------------------------------------
__global__ void __launch_bounds__(512, 2) kernelL(int layer, int srcIdx, int dstIdx, int first) {
    extern __shared__ u64 sh[];
    u64* shC = sh + 8192;
    const int t = threadIdx.x;                 // 9 bits
    const unsigned h = blockIdx.x;             // global bits 13..21 (9 bits)
    const unsigned ghi = h ^ (h >> 1);
    const unsigned c12 = (h & 1u) << 12;
    u64 a[16];

    // Stage the 12 gates' rotation coefficients (qubits 10..21, 36 u64)
    if (t < 36) shC[t] = __ldg(&g_Rpk[layer][10][0] + t);

    const int b12 = t >> 8, t8 = t & 255;
    // ---- Phase A: i = (b12<<12)|(r<<8)|t8 ; reg bits local 8..11 -> qubit 13-k
    if (first) {
#pragma unroll
        for (int r = 0; r < 16; r++) {
            unsigned i = (b12 << 12) | (r << 8) | t8;
            unsigned glo = (i ^ (i >> 1)) ^ c12;
            float2 ph = g_Phi[(ghi << 2) | (glo >> 11)];
            float2 pl = g_Plo[glo & 2047];
            float2 v = cmulf(ph, pl);
            a[r] = pk2(v.x, v.y);
        }
    } else {
        const float2* __restrict__ src = g_state[srcIdx] + ((size_t)ghi << 13);
#pragma unroll
        for (int r = 0; r < 16; r++) {
            unsigned i = (b12 << 12) | (r << 8) | t8;
            unsigned glo = (i ^ (i >> 1)) ^ c12;
            float2 v = __ldg(&src[glo]);
            a[r] = pk2(v.x, v.y);
        }
    }
    // Apply B_l pre-diagonal phase at target index (h<<13)|i
#pragma unroll
    for (int r = 0; r < 16; r++) {
        int ihi = (h << 2) | (b12 << 1) | (r >> 3);
        int ilo = ((r & 7) << 8) | t8;
        float2 w = cmulf(__ldg(&g_BThi[layer][ihi]), __ldg(&g_BTlo[layer][ilo]));
        a[r] = apply_phase(w, a[r]);
    }
    __syncthreads();                            // coefs visible
    gate_on_regbit<0>(shC + (13 - 10) * 3, a);
    gate_on_regbit<1>(shC + (12 - 10) * 3, a);
    gate_on_regbit<2>(shC + (11 - 10) * 3, a);
    gate_on_regbit<3>(shC + (10 - 10) * 3, a);
#pragma unroll
    for (int r = 0; r < 16; r++) sh[SWL((b12 << 12) | (r << 8) | t8)] = a[r];
    __syncthreads();

    // ---- Phase B: i = (t<<4)|r ; reg bits local 0..3 -> qubit 21-k
#pragma unroll
    for (int r = 0; r < 16; r++) a[r] = sh[SWL((t << 4) | r)];
    gate_on_regbit<0>(shC + (21 - 10) * 3, a);
    gate_on_regbit<1>(shC + (20 - 10) * 3, a);
    gate_on_regbit<2>(shC + (19 - 10) * 3, a);
    gate_on_regbit<3>(shC + (18 - 10) * 3, a);
#pragma unroll
    for (int r = 0; r < 16; r++) sh[SWL((t << 4) | r)] = a[r];
    __syncthreads();

    // ---- Phase C: i = (hi5<<8)|(r<<4)|lo4 ; reg bits local 4..7 -> qubit 17-k
    const int hi5 = t >> 4, lo4 = t & 15;
#pragma unroll
    for (int r = 0; r < 16; r++) a[r] = sh[SWL((hi5 << 8) | (r << 4) | lo4)];
    gate_on_regbit<0>(shC + (17 - 10) * 3, a);
    gate_on_regbit<1>(shC + (16 - 10) * 3, a);
    gate_on_regbit<2>(shC + (15 - 10) * 3, a);
    gate_on_regbit<3>(shC + (14 - 10) * 3, a);

    float2* __restrict__ dst = g_state[dstIdx] + ((size_t)h << 13);
#pragma unroll
    for (int r = 0; r < 16; r++) {
        float re, im; unpk2(a[r], re, im);
        dst[(hi5 << 8) | (r << 4) | lo4] = make_float2(re, im);
    }
}

// ---------------------------------------------------------------------------
// H kernel: tile bits {0..2} U {12..21} (8192 amps), 10 real rotations on
// global bits 12..21 (qubits 0..9). blockIdx = global bits 3..11. Store applies
// A_l post-diag phase (layers 1..6) OR folds final CNOT chain + |amp|^2
// (probs != nullptr; A_7 dropped — phase-invariant). 3 phases.
// Local map: local 0..2 = global 0..2, local 3..12 = global 12..21.
// j(i) = ((i>>3)<<12) | (f<<3) | (i&7)
// ---------------------------------------------------------------------------
__global__ void __launch_bounds__(512, 2) kernelH(int layer, int srcIdx, int dstIdx,
                                                  float* __restrict__ probs) {
    extern __shared__ u64 sh[];
    u64* shC = sh + 8192;
    const int t = threadIdx.x;                 // 9 bits
    const unsigned f = blockIdx.x;             // global bits 3..11 (9 bits)
    u64 a[16];

    // Stage the 10 gates' rotation coefficients (qubits 0..9, 30 u64)
    if (t < 30) shC[t] = __ldg(&g_Rpk[layer][0][0] + t);

    // ---- Phase A: i = (r<<9)|t ; reg bits local 9..12 = global 18..21 -> qubit 3-k
    const unsigned jt = ((unsigned)(t >> 3) << 12) | (f << 3) | (unsigned)(t & 7);
    {
        const float2* __restrict__ src = g_state[srcIdx];
#pragma unroll
        for (int r = 0; r < 16; r++) {
            float2 v = __ldg(&src[jt | (r << 18)]);
            a[r] = pk2(v.x, v.y);
        }
    }
    __syncthreads();                            // coefs visible
    gate_on_regbit<0>(shC + 3 * 3, a);
    gate_on_regbit<1>(shC + 2 * 3, a);
    gate_on_regbit<2>(shC + 1 * 3, a);
    gate_on_regbit<3>(shC + 0 * 3, a);
#pragma unroll
    for (int r = 0; r < 16; r++) sh[SWH((r << 9) | t)] = a[r];
    __syncthreads();

    // ---- Phase B: i = (hi4<<9)|(r<<5)|lo5 ; local 5..8 = global 14..17 -> qubit 7-k
    const int hi4 = t >> 5, lo5 = t & 31;
#pragma unroll
    for (int r = 0; r < 16; r++) a[r] = sh[SWH((hi4 << 9) | (r << 5) | lo5)];
    gate_on_regbit<0>(shC + 7 * 3, a);
    gate_on_regbit<1>(shC + 6 * 3, a);
    gate_on_regbit<2>(shC + 5 * 3, a);
    gate_on_regbit<3>(shC + 4 * 3, a);
#pragma unroll
    for (int r = 0; r < 16; r++) sh[SWH((hi4 << 9) | (r << 5) | lo5)] = a[r];
    __syncthreads();

    // ---- Phase C: reg bits: r0,r1 -> local 3,4 (qubits 9,8); r2,r3 -> local 9,10
    // i = (t_c<<11)|(rf<<9)|(t_b<<5)|(rg<<3)|t_a
    const int t_a = t & 7, t_b = (t >> 3) & 15, t_c = t >> 7;
#pragma unroll
    for (int r = 0; r < 16; r++) {
        int i = (t_c << 11) | ((r >> 2) << 9) | (t_b << 5) | ((r & 3) << 3) | t_a;
        a[r] = sh[SWH(i)];
    }
    gate_on_regbit<0>(shC + 9 * 3, a);     // local 3 = global 12 -> qubit 9
    gate_on_regbit<1>(shC + 8 * 3, a);     // local 4 = global 13 -> qubit 8

    if (probs) {
        // layer 7: post-diag dropped (|amp|^2 phase-invariant); fold final CNOT chain
#pragma unroll
        for (int r = 0; r < 16; r++) {
            int i = (t_c << 11) | ((r >> 2) << 9) | (t_b << 5) | ((r & 3) << 3) | t_a;
            unsigned j = (((unsigned)i >> 3) << 12) | (f << 3) | (unsigned)(i & 7);
            unsigned o = j;
            o ^= o >> 1; o ^= o >> 2; o ^= o >> 4; o ^= o >> 8; o ^= o >> 16;
            float re, im; unpk2(a[r], re, im);
            probs[o] = fmaf(re, re, im * im);
        }
    } else {
        float2* __restrict__ dst = g_state[dstIdx];
#pragma unroll
        for (int r = 0; r < 16; r++) {
            int i = (t_c << 11) | ((r >> 2) << 9) | (t_b << 5) | ((r & 3) << 3) | t_a;
            unsigned j = (((unsigned)i >> 3) << 12) | (f << 3) | (unsigned)(i & 7);
            float2 w = cmulf(__ldg(&g_AThi[layer][j >> 11]),
                             __ldg(&g_ATlo[layer][j & 2047]));
            float re, im; unpk2(a[r], re, im);
            dst[j] = make_float2(w.x * re - w.y * im, w.x * im + w.y * re);
        }
    }
}

// ---------------------------------------------------------------------------
extern "C" void kernel_launch(void* const* d_in, const int* in_sizes, int n_in,
                              void* d_out, int out_size) {
    (void)in_sizes; (void)n_in; (void)out_size;
    const float* params = (const float*)d_in[0];
    float* out = (float*)d_out;

    cudaFuncSetAttribute(kernelL, cudaFuncAttributeMaxDynamicSharedMemorySize, SMEM_BYTES);
    cudaFuncSetAttribute(kernelH, cudaFuncAttributeMaxDynamicSharedMemorySize, SMEM_BYTES);

    prep_kernel<<<1, 1024>>>(params);

    // Layer 0 folded into tables; layer-(l-1) CNOT chain folded into L's gray
    // load; layer-7 chain folded into the prob scatter; diagonals folded into
    // load/store phase multiplies.
    kernelL<<<512, 512, SMEM_BYTES>>>(1, /*src*/1, /*dst*/0, /*first*/1);
    kernelH<<<512, 512, SMEM_BYTES>>>(1, 0, 1, nullptr);
    for (int ll = 2; ll <= 7; ll++) {
        kernelL<<<512, 512, SMEM_BYTES>>>(ll, 1, 0, 0);
        kernelH<<<512, 512, SMEM_BYTES>>>(ll, 0, 1, (ll == 7) ? out : nullptr);
    }
}

// round 9
// speedup vs baseline: 1.5005x; 1.1240x over previous
#include <cuda_runtime.h>

#define NQ      22
#define NSTATE  (1u << NQ)
#define NLAYERS 8

typedef unsigned long long u64;

// Ping-pong statevector buffers (64 MB total; resident in L2)
__device__ float2 g_state[2][NSTATE];
// Fused single-qubit unitaries U = RX*RZ*RY (float2, for layer-0 tables)
__device__ float2 g_U[NLAYERS][NQ][4];
// ZYZ real-rotation coefficients per gate: [0]=dup(c) [1]=dup(s) [2]=dup(-s)
__device__ u64 g_Rpk[NLAYERS][NQ][3];
// ZYZ half-angles: U = diag(e^{-ipA},e^{ipA}) * R(c,s) * diag(e^{-ipB},e^{ipB})
__device__ float g_pA[NLAYERS][NQ];
__device__ float g_pB[NLAYERS][NQ];
// Combined inter-layer diagonal tables, applied at L-load of layer L:
//   W_L[t] = B_L[t] * A_{L-1}[gray(t)]      (A term absent for L=1)
// hi: t bits 11..21 (self-contained under gray); lo: t bits 0..10, with
// carry = t_11 feeding gray bit 10.
__device__ float2 g_Whi[NLAYERS][2048];
__device__ float2 g_Wlo[NLAYERS][2][2048];
// Product-state tables for layer 0: amp(g) = Phi[g>>11] * Plo[g & 0x7FF]
__device__ float2 g_Phi[2048];
__device__ float2 g_Plo[2048];

// ---------------------------------------------------------------------------
// f32x2 packed helpers (amplitude packed as (re, im) in a 64-bit reg pair)
// ---------------------------------------------------------------------------
__device__ __forceinline__ u64 pk2(float lo, float hi) {
    u64 r; asm("mov.b64 %0, {%1, %2};" : "=l"(r) : "f"(lo), "f"(hi)); return r;
}
__device__ __forceinline__ void unpk2(u64 v, float& lo, float& hi) {
    asm("mov.b64 {%0, %1}, %2;" : "=f"(lo), "=f"(hi) : "l"(v));
}
__device__ __forceinline__ u64 f2mul(u64 a, u64 b) {
    u64 r; asm("mul.rn.f32x2 %0, %1, %2;" : "=l"(r) : "l"(a), "l"(b)); return r;
}
__device__ __forceinline__ u64 f2fma(u64 a, u64 b, u64 c) {
    u64 r; asm("fma.rn.f32x2 %0, %1, %2, %3;" : "=l"(r) : "l"(a), "l"(b), "l"(c)); return r;
}

__device__ __forceinline__ float2 cmulf(float2 a, float2 b) {
    return make_float2(a.x * b.x - a.y * b.y, a.x * b.y + a.y * b.x);
}
// multiply packed amp by scalar complex phase w
__device__ __forceinline__ u64 apply_phase(float2 w, u64 x) {
    float re, im; unpk2(x, re, im);
    return pk2(w.x * re - w.y * im, w.x * im + w.y * re);
}

// Real Givens butterfly: y0 = c*x0 - s*x1 ; y1 = s*x0 + c*x1  (4 f32x2 ops)
__device__ __forceinline__ void rbfly(u64 c, u64 s, u64 ns, u64& x0, u64& x1) {
    u64 y0 = f2fma(c, x0, f2mul(ns, x1));
    u64 y1 = f2fma(c, x1, f2mul(s, x0));
    x0 = y0; x1 = y1;
}

// Apply one real rotation across register bit K of the 16-amp register file
template<int K>
__device__ __forceinline__ void gate_on_regbit(const u64* Uq, u64 a[16]) {
    u64 c = Uq[0], s = Uq[1], ns = Uq[2];
#pragma unroll
    for (int m = 0; m < 8; m++) {
        int j0 = ((m >> K) << (K + 1)) | (m & ((1 << K) - 1));
        rbfly(c, s, ns, a[j0], a[j0 | (1 << K)]);
    }
}

// Swizzles (verified conflict-free / half-warp-only for each kernel's patterns)
__device__ __forceinline__ int SWL(int i) { return i ^ ((i >> 4) & 15); }   // kernelL
__device__ __forceinline__ int SWH(int i) { return i ^ ((i >> 2) & 24); }   // kernelH

// ---------------------------------------------------------------------------
// Prep stage 1 (1 block): fused U matrices + ZYZ decomposition per gate.
// ---------------------------------------------------------------------------
__global__ void prep_gates(const float* __restrict__ p) {
    int tid = threadIdx.x;
    if (tid >= NLAYERS * NQ) return;
    int l = tid / NQ, q = tid % NQ;
    float ty = p[l * 3 * NQ + q];
    float tz = p[l * 3 * NQ + NQ + q];
    float tx = p[l * 3 * NQ + 2 * NQ + q];
    float cy = cosf(0.5f * ty), sy = sinf(0.5f * ty);
    float cz = cosf(0.5f * tz), sz = sinf(0.5f * tz);
    float cx = cosf(0.5f * tx), sx = sinf(0.5f * tx);
    float2 em = make_float2(cz, -sz);
    float2 ep = make_float2(cz, sz);
    float2 u00 = make_float2(cx * cy * em.x + sx * sy * ep.y,
                             cx * cy * em.y - sx * sy * ep.x);
    float2 u01 = make_float2(-cx * sy * em.x + sx * cy * ep.y,
                             -cx * sy * em.y - sx * cy * ep.x);
    float2 u10 = make_float2(sx * cy * em.y + cx * sy * ep.x,
                             -sx * cy * em.x + cx * sy * ep.y);
    float2 u11 = make_float2(-sx * sy * em.y + cx * cy * ep.x,
                             sx * sy * em.x + cx * cy * ep.y);
    g_U[l][q][0] = u00; g_U[l][q][1] = u01;
    g_U[l][q][2] = u10; g_U[l][q][3] = u11;
    // ZYZ: U = diag(e^{-ipA},e^{ipA}) * [[c,-s],[s,c]] * diag(e^{-ipB},e^{ipB})
    float c = sqrtf(u00.x * u00.x + u00.y * u00.y);
    float s = sqrtf(u01.x * u01.x + u01.y * u01.y);
    float p00 = atan2f(u00.y, u00.x);
    float p01 = atan2f(u01.y, u01.x);
    const float PI = 3.14159265358979f;
    float pA = 0.5f * (-p00 - p01 + PI);
    float pB = 0.5f * (-p00 + p01 - PI);
    g_pA[l][q] = pA; g_pB[l][q] = pB;
    g_Rpk[l][q][0] = pk2(c, c);
    g_Rpk[l][q][1] = pk2(s, s);
    g_Rpk[l][q][2] = pk2(-s, -s);
}

// ---------------------------------------------------------------------------
// Prep stage 2 (grid-parallel): product tables + combined diag tables.
// Flat index cover: [0,2048) Phi/Plo | [2048,2048+7*2048) Whi | rest Wlo.
// Launch with exactly 88*512 = 45056 threads.
// ---------------------------------------------------------------------------
__global__ void prep_tables() {
    int idx = blockIdx.x * blockDim.x + threadIdx.x;
    if (idx < 2048) {
        int i = idx;
        float2 ph = make_float2(1.f, 0.f);
        float2 pl = make_float2(1.f, 0.f);
        for (int q = 0; q <= 10; q++) {
            int b = (i >> (10 - q)) & 1;
            ph = cmulf(ph, g_U[0][q][b * 2]);
        }
        for (int q = 11; q <= 21; q++) {
            int b = (i >> (21 - q)) & 1;
            pl = cmulf(pl, g_U[0][q][b * 2]);
        }
        g_Phi[i] = ph;
        g_Plo[i] = pl;
    } else if (idx < 2048 + 7 * 2048) {
        // Whi[L][x]: x bit k = t_{11+k} <-> qubit 10-k; gray bit 11+k = x_k ^ x_{k+1}
        int k0 = idx - 2048;
        int L = 1 + (k0 >> 11), x = k0 & 2047;
        float ang = 0.f;
        for (int k = 0; k < 11; k++) {
            int xb = (x >> k) & 1;
            ang += (xb ? 1.f : -1.f) * g_pB[L][10 - k];
            if (L >= 2) {
                int gb = xb ^ ((k < 10) ? ((x >> (k + 1)) & 1) : 0);
                ang += (gb ? 1.f : -1.f) * g_pA[L - 1][10 - k];
            }
        }
        float sv, cv; sincosf(ang, &sv, &cv);
        g_Whi[L][x] = make_float2(cv, sv);
    } else if (idx < 2048 + 7 * 2048 + 7 * 2 * 2048) {
        // Wlo[L][carry][x]: x bit b = t_b <-> qubit 21-b; gray bit b = x_b^x_{b+1},
        // gray bit 10 = x_10 ^ carry (carry = t_11)
        int k0 = idx - (2048 + 7 * 2048);
        int L = 1 + (k0 >> 12), carry = (k0 >> 11) & 1, x = k0 & 2047;
        float ang = 0.f;
        for (int b = 0; b < 11; b++) {
            int xb = (x >> b) & 1;
            ang += (xb ? 1.f : -1.f) * g_pB[L][21 - b];
            if (L >= 2) {
                int gb = xb ^ ((b < 10) ? ((x >> (b + 1)) & 1) : carry);
                ang += (gb ? 1.f : -1.f) * g_pA[L - 1][21 - b];
            }
        }
        float sv, cv; sincosf(ang, &sv, &cv);
        g_Wlo[L][carry][x] = make_float2(cv, sv);
    }
}

// Shared memory layout: sh[0..8191] = amplitude tile, sh[8192..] = gate coefs
#define SMEM_WORDS (8192 + 40)
#define SMEM_BYTES (SMEM_WORDS * 8)

// ---------------------------------------------------------------------------
// L kernel: tile = 8192 contiguous amps (bits 0..12), 12 real rotations on
// bits 0..11 (qubits 10..21). Load folds previous layer's CNOT chain via gray
// addressing AND applies the combined diag W_layer = B_layer * A_{layer-1}∘gray;
// first=1 synthesizes the layer-0 product state. 3 phases, 2 smem transposes.
// ---------------------------------------------------------------------------
__global__ void __launch_bounds__(512, 2) kernelL(int layer, int srcIdx, int dstIdx, int first) {
    extern __shared__ u64 sh[];
    u64* shC = sh + 8192;
    const int t = threadIdx.x;                 // 9 bits
    const unsigned h = blockIdx.x;             // global bits 13..21 (9 bits)
    const unsigned ghi = h ^ (h >> 1);
    const unsigned c12 = (h & 1u) << 12;
    u64 a[16];

    // Stage the 12 gates' rotation coefficients (qubits 10..21, 36 u64)
    if (t < 36) shC[t] = __ldg(&g_Rpk[layer][10][0] + t);

    const int b12 = t >> 8, t8 = t & 255;
    // ---- Phase A: i = (b12<<12)|(r<<8)|t8 ; reg bits local 8..11 -> qubit 13-k
    if (first) {
#pragma unroll
        for (int r = 0; r < 16; r++) {
            unsigned i = (b12 << 12) | (r << 8) | t8;
            unsigned glo = (i ^ (i >> 1)) ^ c12;
            float2 ph = g_Phi[(ghi << 2) | (glo >> 11)];
            float2 pl = g_Plo[glo & 2047];
            float2 v = cmulf(ph, pl);
            a[r] = pk2(v.x, v.y);
        }
    } else {
        const float2* __restrict__ src = g_state[srcIdx] + ((size_t)ghi << 13);
#pragma unroll
        for (int r = 0; r < 16; r++) {
            unsigned i = (b12 << 12) | (r << 8) | t8;
            unsigned glo = (i ^ (i >> 1)) ^ c12;
            float2 v = __ldg(&src[glo]);
            a[r] = pk2(v.x, v.y);
        }
    }
    // Apply combined diag W_layer at target index (h<<13)|i.
    // xhi = t>>11 = (h<<2)|(b12<<1)|(r>>3); carry = t_11 = r>>3; xlo = i&2047.
    {
        const float2 whi0 = __ldg(&g_Whi[layer][(h << 2) | (b12 << 1)]);
        const float2 whi1 = __ldg(&g_Whi[layer][(h << 2) | (b12 << 1) | 1]);
#pragma unroll
        for (int r = 0; r < 16; r++) {
            int carry = r >> 3;
            int ilo = ((r & 7) << 8) | t8;
            float2 w = cmulf(carry ? whi1 : whi0, __ldg(&g_Wlo[layer][carry][ilo]));
            a[r] = apply_phase(w, a[r]);
        }
    }
    __syncthreads();                            // coefs visible
    gate_on_regbit<0>(shC + (13 - 10) * 3, a);
    gate_on_regbit<1>(shC + (12 - 10) * 3, a);
    gate_on_regbit<2>(shC + (11 - 10) * 3, a);
    gate_on_regbit<3>(shC + (10 - 10) * 3, a);
#pragma unroll
    for (int r = 0; r < 16; r++) sh[SWL((b12 << 12) | (r << 8) | t8)] = a[r];
    __syncthreads();

    // ---- Phase B: i = (t<<4)|r ; reg bits local 0..3 -> qubit 21-k
#pragma unroll
    for (int r = 0; r < 16; r++) a[r] = sh[SWL((t << 4) | r)];
    gate_on_regbit<0>(shC + (21 - 10) * 3, a);
    gate_on_regbit<1>(shC + (20 - 10) * 3, a);
    gate_on_regbit<2>(shC + (19 - 10) * 3, a);
    gate_on_regbit<3>(shC + (18 - 10) * 3, a);
#pragma unroll
    for (int r = 0; r < 16; r++) sh[SWL((t << 4) | r)] = a[r];
    __syncthreads();

    // ---- Phase C: i = (hi5<<8)|(r<<4)|lo4 ; reg bits local 4..7 -> qubit 17-k
    const int hi5 = t >> 4, lo4 = t & 15;
#pragma unroll
    for (int r = 0; r < 16; r++) a[r] = sh[SWL((hi5 << 8) | (r << 4) | lo4)];
    gate_on_regbit<0>(shC + (17 - 10) * 3, a);
    gate_on_regbit<1>(shC + (16 - 10) * 3, a);
    gate_on_regbit<2>(shC + (15 - 10) * 3, a);
    gate_on_regbit<3>(shC + (14 - 10) * 3, a);

    float2* __restrict__ dst = g_state[dstIdx] + ((size_t)h << 13);
#pragma unroll
    for (int r = 0; r < 16; r++) {
        float re, im; unpk2(a[r], re, im);
        dst[(hi5 << 8) | (r << 4) | lo4] = make_float2(re, im);
    }
}

// ---------------------------------------------------------------------------
// H kernel: tile bits {0..2} U {12..21} (8192 amps), 10 real rotations on
// global bits 12..21 (qubits 0..9). blockIdx = global bits 3..11. Store is
// plain (post-diag A_l deferred into next layer's W table) OR folds final
// CNOT chain + |amp|^2 (probs != nullptr; A_7 dropped — phase-invariant).
// Local map: local 0..2 = global 0..2, local 3..12 = global 12..21.
// j(i) = ((i>>3)<<12) | (f<<3) | (i&7)
// ---------------------------------------------------------------------------
__global__ void __launch_bounds__(512, 2) kernelH(int layer, int srcIdx, int dstIdx,
                                                  float* __restrict__ probs) {
    extern __shared__ u64 sh[];
    u64* shC = sh + 8192;
    const int t = threadIdx.x;                 // 9 bits
    const unsigned f = blockIdx.x;             // global bits 3..11 (9 bits)
    u64 a[16];

    // Stage the 10 gates' rotation coefficients (qubits 0..9, 30 u64)
    if (t < 30) shC[t] = __ldg(&g_Rpk[layer][0][0] + t);

    // ---- Phase A: i = (r<<9)|t ; reg bits local 9..12 = global 18..21 -> qubit 3-k
    const unsigned jt = ((unsigned)(t >> 3) << 12) | (f << 3) | (unsigned)(t & 7);
    {
        const float2* __restrict__ src = g_state[srcIdx];
#pragma unroll
        for (int r = 0; r < 16; r++) {
            float2 v = __ldg(&src[jt | (r << 18)]);
            a[r] = pk2(v.x, v.y);
        }
    }
    __syncthreads();                            // coefs visible
    gate_on_regbit<0>(shC + 3 * 3, a);
    gate_on_regbit<1>(shC + 2 * 3, a);
    gate_on_regbit<2>(shC + 1 * 3, a);
    gate_on_regbit<3>(shC + 0 * 3, a);
#pragma unroll
    for (int r = 0; r < 16; r++) sh[SWH((r << 9) | t)] = a[r];
    __syncthreads();

    // ---- Phase B: i = (hi4<<9)|(r<<5)|lo5 ; local 5..8 = global 14..17 -> qubit 7-k
    const int hi4 = t >> 5, lo5 = t & 31;
#pragma unroll
    for (int r = 0; r < 16; r++) a[r] = sh[SWH((hi4 << 9) | (r << 5) | lo5)];
    gate_on_regbit<0>(shC + 7 * 3, a);
    gate_on_regbit<1>(shC + 6 * 3, a);
    gate_on_regbit<2>(shC + 5 * 3, a);
    gate_on_regbit<3>(shC + 4 * 3, a);
#pragma unroll
    for (int r = 0; r < 16; r++) sh[SWH((hi4 << 9) | (r << 5) | lo5)] = a[r];
    __syncthreads();

    // ---- Phase C: reg bits: r0,r1 -> local 3,4 (qubits 9,8); r2,r3 -> local 9,10
    // i = (t_c<<11)|(rf<<9)|(t_b<<5)|(rg<<3)|t_a
    const int t_a = t & 7, t_b = (t >> 3) & 15, t_c = t >> 7;
#pragma unroll
    for (int r = 0; r < 16; r++) {
        int i = (t_c << 11) | ((r >> 2) << 9) | (t_b << 5) | ((r & 3) << 3) | t_a;
        a[r] = sh[SWH(i)];
    }
    gate_on_regbit<0>(shC + 9 * 3, a);     // local 3 = global 12 -> qubit 9
    gate_on_regbit<1>(shC + 8 * 3, a);     // local 4 = global 13 -> qubit 8

    if (probs) {
        // layer 7: post-diag dropped (|amp|^2 phase-invariant); fold final CNOT chain
#pragma unroll
        for (int r = 0; r < 16; r++) {
            int i = (t_c << 11) | ((r >> 2) << 9) | (t_b << 5) | ((r & 3) << 3) | t_a;
            unsigned j = (((unsigned)i >> 3) << 12) | (f << 3) | (unsigned)(i & 7);
            unsigned o = j;
            o ^= o >> 1; o ^= o >> 2; o ^= o >> 4; o ^= o >> 8; o ^= o >> 16;
            float re, im; unpk2(a[r], re, im);
            probs[o] = fmaf(re, re, im * im);
        }
    } else {
        float2* __restrict__ dst = g_state[dstIdx];
#pragma unroll
        for (int r = 0; r < 16; r++) {
            int i = (t_c << 11) | ((r >> 2) << 9) | (t_b << 5) | ((r & 3) << 3) | t_a;
            unsigned j = (((unsigned)i >> 3) << 12) | (f << 3) | (unsigned)(i & 7);
            float re, im; unpk2(a[r], re, im);
            dst[j] = make_float2(re, im);
        }
    }
}

// ---------------------------------------------------------------------------
extern "C" void kernel_launch(void* const* d_in, const int* in_sizes, int n_in,
                              void* d_out, int out_size) {
    (void)in_sizes; (void)n_in; (void)out_size;
    const float* params = (const float*)d_in[0];
    float* out = (float*)d_out;

    cudaFuncSetAttribute(kernelL, cudaFuncAttributeMaxDynamicSharedMemorySize, SMEM_BYTES);
    cudaFuncSetAttribute(kernelH, cudaFuncAttributeMaxDynamicSharedMemorySize, SMEM_BYTES);

    prep_gates<<<1, 192>>>(params);
    prep_tables<<<88, 512>>>();

    // Layer 0 folded into tables; layer-(l-1) CNOT chain folded into L's gray
    // load; layer-7 chain folded into the prob scatter; both diagonals of each
    // layer boundary folded into ONE combined phase multiply at L-load.
    kernelL<<<512, 512, SMEM_BYTES>>>(1, /*src*/1, /*dst*/0, /*first*/1);
    kernelH<<<512, 512, SMEM_BYTES>>>(1, 0, 1, nullptr);
    for (int ll = 2; ll <= 7; ll++) {
        kernelL<<<512, 512, SMEM_BYTES>>>(ll, 1, 0, 0);
        kernelH<<<512, 512, SMEM_BYTES>>>(ll, 0, 1, (ll == 7) ? out : nullptr);
    }
}